// round 3
// baseline (speedup 1.0000x reference)
#include <cuda_runtime.h>
#include <math.h>

#define NB 8
#define NL 48
#define NT 512
#define HD 128
#define NG 10
#define M_TOTAL (NB*NL*NT)          // 196608

#define OFF_PI  0
#define OFF_SIG (M_TOTAL*NG)
#define OFF_MU  (2*M_TOTAL*NG)
#define OFF_D   (3*M_TOTAL*NG)
#define OFF_CB  (3*M_TOTAL*NG + M_TOTAL)

// scratch (device globals: no allocation)
__device__ float g_Al[NB*NL*HD];    // 384 x 128
__device__ float g_At[NB*NT*HD];    // 4096 x 128

__device__ __forceinline__ float elu1(float x) {
    return x > 0.0f ? x : (__expf(x) - 1.0f);
}

// pack (x,x) into one 64-bit f32x2 register pair
__device__ __forceinline__ unsigned long long dup2(float x) {
    unsigned long long r;
    asm("mov.b64 %0, {%1, %1};" : "=l"(r) : "r"(__float_as_uint(x)));
    return r;
}
// d = a * b + d on two packed fp32 lanes (FFMA2 — PTX-only on sm_103a)
__device__ __forceinline__ void fma2(unsigned long long& d,
                                     unsigned long long a, unsigned long long b) {
    asm("fma.rn.f32x2 %0, %1, %2, %0;" : "+l"(d) : "l"(a), "l"(b));
}
__device__ __forceinline__ void unpack2(unsigned long long v, float& lo, float& hi) {
    unsigned a, b;
    asm("mov.b64 {%0, %1}, %2;" : "=r"(a), "=r"(b) : "l"(v));
    lo = __uint_as_float(a); hi = __uint_as_float(b);
}

// ---------------------------------------------------------------------------
// Precompute: A_l = s*(lig_s@W1^T + b1 - mean) + beta ;  A_t = s*(pro_s@W1^T)
// ---------------------------------------------------------------------------
#define PRE_ROWS 32
#define PRE_THREADS 256
#define W1T_PITCH 132
#define PRE_SMEM ((PRE_ROWS*HD + HD*W1T_PITCH)*sizeof(float))

__global__ void __launch_bounds__(PRE_THREADS)
precompute_kernel(const float* __restrict__ lig_s, const float* __restrict__ pro_s,
                  const float* __restrict__ W1,    const float* __restrict__ b1,
                  const float* __restrict__ bn_g,  const float* __restrict__ bn_b,
                  const float* __restrict__ bn_m,  const float* __restrict__ bn_v)
{
    extern __shared__ float sm[];
    float* Xs  = sm;                      // [32][128]
    float* W1t = sm + PRE_ROWS*HD;        // [128][132]  (transposed, padded)

    const int tid  = threadIdx.x;
    const int row0 = blockIdx.x * PRE_ROWS;
    const bool is_lig = (row0 < NB*NL);

    const float4* src = is_lig ? (const float4*)(lig_s + (size_t)row0*HD)
                               : (const float4*)(pro_s + (size_t)(row0 - NB*NL)*HD);
    float4* Xs4 = (float4*)Xs;
    #pragma unroll
    for (int i = 0; i < (PRE_ROWS*HD/4)/PRE_THREADS; i++)
        Xs4[tid + i*PRE_THREADS] = src[tid + i*PRE_THREADS];

    for (int idx = tid; idx < HD*HD; idx += PRE_THREADS) {
        int h = idx >> 7, k = idx & (HD-1);
        W1t[k*W1T_PITCH + h] = W1[idx];
    }
    __syncthreads();

    const int r  = tid >> 3;
    const int h0 = (tid & 7) << 4;

    float acc[16];
    #pragma unroll
    for (int j = 0; j < 16; j++) acc[j] = 0.0f;

    #pragma unroll 4
    for (int k = 0; k < HD; k++) {
        float x = Xs[r*HD + k];
        const float4* w4 = (const float4*)(&W1t[k*W1T_PITCH + h0]);
        float w[16];
        #pragma unroll
        for (int q = 0; q < 4; q++) {
            float4 v = w4[q];
            w[4*q] = v.x; w[4*q+1] = v.y; w[4*q+2] = v.z; w[4*q+3] = v.w;
        }
        #pragma unroll
        for (int j = 0; j < 16; j++) acc[j] = fmaf(x, w[j], acc[j]);
    }

    const int row = row0 + r;
    if (is_lig) {
        #pragma unroll
        for (int j = 0; j < 16; j++) {
            int h = h0 + j;
            float s = bn_g[h] * rsqrtf(bn_v[h] + 1e-5f);
            g_Al[row*HD + h] = s * (acc[j] + b1[h] - bn_m[h]) + bn_b[h];
        }
    } else {
        const int prow = row - NB*NL;
        #pragma unroll
        for (int j = 0; j < 16; j++) {
            int h = h0 + j;
            float s = bn_g[h] * rsqrtf(bn_v[h] + 1e-5f);
            g_At[prow*HD + h] = s * acc[j];
        }
    }
}

// ---------------------------------------------------------------------------
// Main pair kernel (packed f32x2 heads).
// Tile: 8 ligands x 64 proteins per block, 256 threads, 2 pairs/thread.
// Heads packed (g, g+1) per 64-bit lane pair: weights load straight from smem
// as 16B -> two f32x2 operands; activation e is duplicated with 1 mov.b64.
// ---------------------------------------------------------------------------
#define L_TILE 8
#define T_TILE 64
#define AT_PITCH 132          // floats; 33 float4 (odd) -> phase-conflict-free
#define SW_PITCH 36           // floats per h-row: 30 weights + 2 zero pads + align
#define MAIN_THREADS 256

// dynamic smem layout (floats)
#define SM_AL   0
#define SM_AT   (SM_AL + L_TILE*HD)                // 1024
#define SM_W    (SM_AT + T_TILE*AT_PITCH)          // 1024 + 8448 = 9472
#define SM_BIAS (SM_W + HD*SW_PITCH)               // 9472 + 4608 = 14080
#define SM_PL   (SM_BIAS + 32)                     // 14112
#define SM_PT   (SM_PL + L_TILE*4)                 // 14144
#define SM_TOT  (SM_PT + T_TILE*4)                 // 14400 floats = 57600 B

__global__ void __launch_bounds__(MAIN_THREADS)
pair_kernel(const float* __restrict__ lig_pos, const float* __restrict__ pro_pos,
            const float* __restrict__ W_pi,  const float* __restrict__ b_pi,
            const float* __restrict__ W_sig, const float* __restrict__ b_sig,
            const float* __restrict__ W_mu,  const float* __restrict__ b_mu,
            float* __restrict__ out)
{
    extern __shared__ float sm[];
    float* sAl   = sm + SM_AL;
    float* sAt   = sm + SM_AT;
    float* sW    = sm + SM_W;
    float* sBias = sm + SM_BIAS;
    float* sPl   = sm + SM_PL;
    float* sPt   = sm + SM_PT;

    const int tid = threadIdx.x;
    const int b  = blockIdx.z;
    const int l0 = blockIdx.y * L_TILE;
    const int t0 = blockIdx.x * T_TILE;

    {   // ligand rows: 8 x 128 floats
        const float4* srl = (const float4*)(g_Al + (size_t)(b*NL + l0)*HD);
        float4* dl = (float4*)sAl;
        if (tid < L_TILE*HD/4) dl[tid] = srl[tid];
    }
    {   // protein rows: 64 x 128 floats -> padded pitch
        const float4* srt = (const float4*)(g_At + (size_t)(b*NT + t0)*HD);
        float4* dt = (float4*)sAt;     // pitch 33 float4
        #pragma unroll
        for (int i = 0; i < (T_TILE*HD/4)/MAIN_THREADS; i++) {
            int idx = tid + i*MAIN_THREADS;
            int t = idx >> 5, hq = idx & 31;
            dt[t*(AT_PITCH/4) + hq] = srt[idx];
        }
    }
    // head weights, interleaved per h: [pi0..pi9, sig0..sig9, mu0..mu9, 0, 0]
    for (int idx = tid; idx < NG*HD; idx += MAIN_THREADS) {
        int g = idx >> 7, h = idx & (HD-1);
        sW[h*SW_PITCH + g]      = W_pi[idx];
        sW[h*SW_PITCH + 10 + g] = W_sig[idx];
        sW[h*SW_PITCH + 20 + g] = W_mu[idx];
    }
    if (tid < HD) { sW[tid*SW_PITCH + 30] = 0.0f; sW[tid*SW_PITCH + 31] = 0.0f; }
    if (tid < NG) {
        sBias[tid]      = b_pi[tid];
        sBias[10 + tid] = b_sig[tid];
        sBias[20 + tid] = b_mu[tid];
    }
    if (tid < L_TILE*3) {
        int l = tid / 3, c = tid % 3;
        sPl[l*4 + c] = lig_pos[(size_t)(b*NL + l0 + l)*3 + c];
    }
    for (int idx = tid; idx < T_TILE*3; idx += MAIN_THREADS) {
        int t = idx / 3, c = idx % 3;
        sPt[t*4 + c] = pro_pos[(size_t)(b*NT + t0 + t)*3 + c];
    }
    __syncthreads();

    const int lt = tid >> 5;    // 0..7
    const int tt = tid & 31;    // 0..31 ; pairs (lt,tt) and (lt,tt+32)

    // 15 packed accumulators per pair: lanes (g, g+1), g even, covering 30 heads
    unsigned long long acc0[15], acc1[15];
    #pragma unroll
    for (int q = 0; q < 15; q++) { acc0[q] = 0ull; acc1[q] = 0ull; }

    const float4* al4 = (const float4*)(sAl + lt*HD);
    const float4* a04 = (const float4*)(sAt + tt*AT_PITCH);
    const float4* a14 = (const float4*)(sAt + (tt+32)*AT_PITCH);

    #pragma unroll 2
    for (int hq = 0; hq < HD/4; hq++) {
        float4 al = al4[hq];
        float4 v0 = a04[hq];
        float4 v1 = a14[hq];
        float e0[4], e1[4];
        e0[0] = elu1(al.x + v0.x); e0[1] = elu1(al.y + v0.y);
        e0[2] = elu1(al.z + v0.z); e0[3] = elu1(al.w + v0.w);
        e1[0] = elu1(al.x + v1.x); e1[1] = elu1(al.y + v1.y);
        e1[2] = elu1(al.z + v1.z); e1[3] = elu1(al.w + v1.w);
        #pragma unroll
        for (int j = 0; j < 4; j++) {
            // 30 weights + 2 pads = 8 x 16B loads = 16 packed f32x2 operands
            const ulonglong2* wr = (const ulonglong2*)(sW + (hq*4 + j)*SW_PITCH);
            unsigned long long wv[16];
            #pragma unroll
            for (int q = 0; q < 8; q++) {
                ulonglong2 v = wr[q];
                wv[2*q] = v.x; wv[2*q+1] = v.y;
            }
            unsigned long long ea = dup2(e0[j]);
            unsigned long long eb = dup2(e1[j]);
            #pragma unroll
            for (int q = 0; q < 15; q++) {
                fma2(acc0[q], ea, wv[q]);
                fma2(acc1[q], eb, wv[q]);
            }
        }
    }

    const int l = l0 + lt;
    const float plx = sPl[lt*4], ply = sPl[lt*4+1], plz = sPl[lt*4+2];

#define DO_PAIR(ACC, TLOC) do {                                               \
    const int tl = (TLOC);                                                    \
    const int t  = t0 + tl;                                                   \
    const size_t p = (size_t)((b*NL + l)*NT) + t;                             \
    float r[30];                                                              \
    _Pragma("unroll")                                                         \
    for (int q = 0; q < 15; q++) unpack2(ACC[q], r[2*q], r[2*q+1]);           \
    float y[10]; float mx = -1e30f;                                           \
    _Pragma("unroll")                                                         \
    for (int g = 0; g < NG; g++) { y[g] = r[g] + sBias[g]; mx = fmaxf(mx, y[g]); } \
    float ssum = 0.0f;                                                        \
    _Pragma("unroll")                                                         \
    for (int g = 0; g < NG; g++) { y[g] = __expf(y[g] - mx); ssum += y[g]; }  \
    float inv = 1.0f / ssum;                                                  \
    float2* po = (float2*)(out + OFF_PI + p*NG);                              \
    _Pragma("unroll")                                                         \
    for (int g = 0; g < 5; g++) po[g] = make_float2(y[2*g]*inv, y[2*g+1]*inv);\
    float2* so = (float2*)(out + OFF_SIG + p*NG);                             \
    _Pragma("unroll")                                                         \
    for (int g = 0; g < 5; g++) {                                             \
        float s0 = elu1(r[10+2*g]   + sBias[10+2*g])   + 1.1f;                \
        float s1 = elu1(r[10+2*g+1] + sBias[10+2*g+1]) + 1.1f;                \
        so[g] = make_float2(s0, s1);                                          \
    }                                                                         \
    float2* mo = (float2*)(out + OFF_MU + p*NG);                              \
    _Pragma("unroll")                                                         \
    for (int g = 0; g < 5; g++) {                                             \
        float m0 = elu1(r[20+2*g]   + sBias[20+2*g])   + 1.0f;                \
        float m1 = elu1(r[20+2*g+1] + sBias[20+2*g+1]) + 1.0f;                \
        mo[g] = make_float2(m0, m1);                                          \
    }                                                                         \
    float dx = plx - sPt[tl*4];                                               \
    float dy = ply - sPt[tl*4+1];                                             \
    float dz = plz - sPt[tl*4+2];                                             \
    out[OFF_D  + p] = sqrtf(dx*dx + dy*dy + dz*dz);                           \
    out[OFF_CB + p] = (float)b;                                               \
} while (0)

    DO_PAIR(acc0, tt);
    DO_PAIR(acc1, tt + 32);
#undef DO_PAIR
}

// ---------------------------------------------------------------------------
extern "C" void kernel_launch(void* const* d_in, const int* in_sizes, int n_in,
                              void* d_out, int out_size)
{
    (void)in_sizes; (void)n_in; (void)out_size;
    const float* lig_s   = (const float*)d_in[0];
    const float* lig_pos = (const float*)d_in[1];
    const float* pro_s   = (const float*)d_in[3];
    const float* pro_pos = (const float*)d_in[4];
    const float* W1      = (const float*)d_in[6];
    const float* b1      = (const float*)d_in[7];
    const float* bn_g    = (const float*)d_in[8];
    const float* bn_b    = (const float*)d_in[9];
    const float* bn_m    = (const float*)d_in[10];
    const float* bn_v    = (const float*)d_in[11];
    const float* W_pi    = (const float*)d_in[12];
    const float* b_pi    = (const float*)d_in[13];
    const float* W_sig   = (const float*)d_in[14];
    const float* b_sig   = (const float*)d_in[15];
    const float* W_mu    = (const float*)d_in[16];
    const float* b_mu    = (const float*)d_in[17];
    float* out = (float*)d_out;

    cudaFuncSetAttribute(precompute_kernel,
                         cudaFuncAttributeMaxDynamicSharedMemorySize, (int)PRE_SMEM);
    precompute_kernel<<<(NB*NL + NB*NT)/PRE_ROWS, PRE_THREADS, PRE_SMEM>>>(
        lig_s, pro_s, W1, b1, bn_g, bn_b, bn_m, bn_v);

    cudaFuncSetAttribute(pair_kernel,
                         cudaFuncAttributeMaxDynamicSharedMemorySize, SM_TOT*(int)sizeof(float));
    pair_kernel<<<dim3(NT/T_TILE, NL/L_TILE, NB), MAIN_THREADS, SM_TOT*sizeof(float)>>>(
        lig_pos, pro_pos, W_pi, b_pi, W_sig, b_sig, W_mu, b_mu, out);
}

// round 5
// speedup vs baseline: 1.2111x; 1.2111x over previous
#include <cuda_runtime.h>
#include <cuda_bf16.h>
#include <math.h>
#include <stdint.h>

#define NB 8
#define NL 48
#define NT 512
#define HD 128
#define NG 10
#define M_TOTAL (NB*NL*NT)          // 196608

#define OFF_PI  0
#define OFF_SIG (M_TOTAL*NG)
#define OFF_MU  (2*M_TOTAL*NG)
#define OFF_D   (3*M_TOTAL*NG)
#define OFF_CB  (3*M_TOTAL*NG + M_TOTAL)

// scratch (device globals: no allocation)
__device__ float g_Al[NB*NL*HD];    // 384 x 128
__device__ float g_At[NB*NT*HD];    // 4096 x 128

__device__ __forceinline__ float elu1(float x) {
    return x > 0.0f ? x : (__expf(x) - 1.0f);
}

// split two fp32 into bf16 hi (truncate) + bf16 lo (round of residual),
// packed k-adjacent: {lo16 = elem k, hi16 = elem k+1}
__device__ __forceinline__ void split2(float e0, float e1, uint32_t& hi, uint32_t& lo) {
    uint32_t u0 = __float_as_uint(e0) & 0xffff0000u;
    uint32_t u1 = __float_as_uint(e1) & 0xffff0000u;
    hi = __byte_perm(u0, u1, 0x7632);
    float f0 = e0 - __uint_as_float(u0);
    float f1 = e1 - __uint_as_float(u1);
    asm("cvt.rn.bf16x2.f32 %0, %1, %2;" : "=r"(lo) : "f"(f1), "f"(f0));
}

// warp-level bf16 MMA, d += a*b  (baseline PTX, works on plain sm_103 target)
__device__ __forceinline__ void mma_bf16(float* d, const uint32_t* a, const uint32_t* b) {
    asm volatile("mma.sync.aligned.m16n8k16.row.col.f32.bf16.bf16.f32 "
        "{%0,%1,%2,%3}, {%4,%5,%6,%7}, {%8,%9}, {%0,%1,%2,%3};"
        : "+f"(d[0]), "+f"(d[1]), "+f"(d[2]), "+f"(d[3])
        : "r"(a[0]), "r"(a[1]), "r"(a[2]), "r"(a[3]), "r"(b[0]), "r"(b[1]));
}

// ---------------------------------------------------------------------------
// Precompute: A_l = s*(lig_s@W1^T + b1 - mean) + beta ;  A_t = s*(pro_s@W1^T)
// ---------------------------------------------------------------------------
#define PRE_ROWS 32
#define PRE_THREADS 256
#define W1T_PITCH 132
#define PRE_SMEM ((PRE_ROWS*HD + HD*W1T_PITCH)*sizeof(float))

__global__ void __launch_bounds__(PRE_THREADS)
precompute_kernel(const float* __restrict__ lig_s, const float* __restrict__ pro_s,
                  const float* __restrict__ W1,    const float* __restrict__ b1,
                  const float* __restrict__ bn_g,  const float* __restrict__ bn_b,
                  const float* __restrict__ bn_m,  const float* __restrict__ bn_v)
{
    extern __shared__ float sm[];
    float* Xs  = sm;
    float* W1t = sm + PRE_ROWS*HD;

    const int tid  = threadIdx.x;
    const int row0 = blockIdx.x * PRE_ROWS;
    const bool is_lig = (row0 < NB*NL);

    const float4* src = is_lig ? (const float4*)(lig_s + (size_t)row0*HD)
                               : (const float4*)(pro_s + (size_t)(row0 - NB*NL)*HD);
    float4* Xs4 = (float4*)Xs;
    #pragma unroll
    for (int i = 0; i < (PRE_ROWS*HD/4)/PRE_THREADS; i++)
        Xs4[tid + i*PRE_THREADS] = src[tid + i*PRE_THREADS];

    for (int idx = tid; idx < HD*HD; idx += PRE_THREADS) {
        int h = idx >> 7, k = idx & (HD-1);
        W1t[k*W1T_PITCH + h] = W1[idx];
    }
    __syncthreads();

    const int r  = tid >> 3;
    const int h0 = (tid & 7) << 4;

    float acc[16];
    #pragma unroll
    for (int j = 0; j < 16; j++) acc[j] = 0.0f;

    #pragma unroll 4
    for (int k = 0; k < HD; k++) {
        float x = Xs[r*HD + k];
        const float4* w4 = (const float4*)(&W1t[k*W1T_PITCH + h0]);
        float w[16];
        #pragma unroll
        for (int q = 0; q < 4; q++) {
            float4 v = w4[q];
            w[4*q] = v.x; w[4*q+1] = v.y; w[4*q+2] = v.z; w[4*q+3] = v.w;
        }
        #pragma unroll
        for (int j = 0; j < 16; j++) acc[j] = fmaf(x, w[j], acc[j]);
    }

    const int row = row0 + r;
    if (is_lig) {
        #pragma unroll
        for (int j = 0; j < 16; j++) {
            int h = h0 + j;
            float s = bn_g[h] * rsqrtf(bn_v[h] + 1e-5f);
            g_Al[row*HD + h] = s * (acc[j] + b1[h] - bn_m[h]) + bn_b[h];
        }
    } else {
        const int prow = row - NB*NL;
        #pragma unroll
        for (int j = 0; j < 16; j++) {
            int h = h0 + j;
            float s = bn_g[h] * rsqrtf(bn_v[h] + 1e-5f);
            g_At[prow*HD + h] = s * acc[j];
        }
    }
}

// ---------------------------------------------------------------------------
// Pair kernel via mma.sync (HMMA bf16, 2-term split, 3 passes).
// Block = 8 ligands x 32 proteins = 256 pairs, 8 warps, warp = 1 lig x 32 prot.
// A fragments (E = elu(Al+At)) built directly in registers — no E staging.
// W head-weight B-fragments pre-split into smem once per block.
// ---------------------------------------------------------------------------
#define THREADS 256
#define AT_P 136              // float pitch for At/Al staging (mod 32 == 8)

// smem float offsets
#define F_AT   0              // 32 x 136
#define F_AL   4352           // 8 x 136
#define F_WHI  5440           // 1024 uint2 = 2048 f
#define F_WLO  7488           // 2048 f
#define F_D    9536           // 256 x 34
#define F_BIAS 18240          // 32
#define F_PL   18272          // 8 x 4
#define F_PT   18304          // 32 x 4
#define SMF    18432          // floats -> 73728 bytes

__device__ __forceinline__ float wval(int n, int k, const float* __restrict__ wp,
                                      const float* __restrict__ ws,
                                      const float* __restrict__ wm) {
    if (n < 10) return wp[n*HD + k];
    if (n < 20) return ws[(n-10)*HD + k];
    if (n < 30) return wm[(n-20)*HD + k];
    return 0.0f;
}

__global__ void __launch_bounds__(THREADS)
pair_kernel(const float* __restrict__ lig_pos, const float* __restrict__ pro_pos,
            const float* __restrict__ W_pi,  const float* __restrict__ b_pi,
            const float* __restrict__ W_sig, const float* __restrict__ b_sig,
            const float* __restrict__ W_mu,  const float* __restrict__ b_mu,
            float* __restrict__ out)
{
    extern __shared__ float sm[];
    const int tid  = threadIdx.x;
    const int w    = tid >> 5;           // warp = local ligand 0..7
    const int lane = tid & 31;
    const int r    = lane >> 2;          // 0..7
    const int q    = lane & 3;           // 0..3
    const int b    = blockIdx.z;
    const int l0   = blockIdx.y * 8;
    const int t0   = blockIdx.x * 32;

    // ---- stage At (32 rows) and Al (8 rows), fp32, pitch 136 ----
    {
        const float4* src = (const float4*)(g_At + (size_t)(b*NT + t0)*HD);
        float4* dst = (float4*)&sm[F_AT];          // pitch 34 float4
        #pragma unroll
        for (int i = 0; i < 4; i++) {
            int idx = tid + i*THREADS;              // < 1024
            dst[(idx >> 5)*34 + (idx & 31)] = src[idx];
        }
    }
    {
        const float4* src = (const float4*)(g_Al + (size_t)(b*NL + l0)*HD);
        float4* dst = (float4*)&sm[F_AL];
        dst[(tid >> 5)*34 + (tid & 31)] = src[tid]; // 256 float4
    }
    // ---- pre-split W into per-lane B fragments ----
    {
        uint2* wh = (uint2*)&sm[F_WHI];
        uint2* wl = (uint2*)&sm[F_WLO];
        #pragma unroll
        for (int e = 0; e < 4; e++) {
            int idx = tid + e*THREADS;              // < 1024 = [kc 8][nc 4][lane 32]
            int kc = idx >> 7, nc = (idx >> 5) & 3, ln = idx & 31;
            int n = nc*8 + (ln >> 2);
            int k = kc*16 + 2*(ln & 3);
            float w0 = wval(n, k,   W_pi, W_sig, W_mu);
            float w1 = wval(n, k+1, W_pi, W_sig, W_mu);
            float w8 = wval(n, k+8, W_pi, W_sig, W_mu);
            float w9 = wval(n, k+9, W_pi, W_sig, W_mu);
            uint32_t h0, lo0, h1, lo1;
            split2(w0, w1, h0, lo0);
            split2(w8, w9, h1, lo1);
            wh[idx] = make_uint2(h0, h1);
            wl[idx] = make_uint2(lo0, lo1);
        }
    }
    if (tid < NG) {
        sm[F_BIAS + tid]      = b_pi[tid];
        sm[F_BIAS + 10 + tid] = b_sig[tid];
        sm[F_BIAS + 20 + tid] = b_mu[tid];
    }
    if (tid < 24) {
        int l = tid / 3, c = tid % 3;
        sm[F_PL + l*4 + c] = lig_pos[(size_t)(b*NL + l0 + l)*3 + c];
    }
    if (tid < 96) {
        int t = tid / 3, c = tid % 3;
        sm[F_PT + t*4 + c] = pro_pos[(size_t)(b*NT + t0 + t)*3 + c];
    }
    __syncthreads();

    // ---- mainloop: warp computes D[32 pairs][32 heads] for its ligand ----
    float D[2][4][4];
    #pragma unroll
    for (int mt = 0; mt < 2; mt++)
        #pragma unroll
        for (int nc = 0; nc < 4; nc++)
            #pragma unroll
            for (int j = 0; j < 4; j++) D[mt][nc][j] = 0.0f;

    const float* alr = &sm[F_AL + w*AT_P];
    const uint2* wh2 = (const uint2*)&sm[F_WHI];
    const uint2* wl2 = (const uint2*)&sm[F_WLO];

    #pragma unroll 2
    for (int kc = 0; kc < 8; kc++) {
        const int kb = kc*16 + 2*q;
        float2 L0 = *(const float2*)(alr + kb);
        float2 L8 = *(const float2*)(alr + kb + 8);
        uint32_t ah[2][4], av[2][4];
        #pragma unroll
        for (int mt = 0; mt < 2; mt++) {
            const float* at0 = &sm[F_AT + (mt*16 + r)*AT_P];
            const float* at8 = at0 + 8*AT_P;
            float2 t00 = *(const float2*)(at0 + kb);
            float2 t08 = *(const float2*)(at0 + kb + 8);
            float2 t80 = *(const float2*)(at8 + kb);
            float2 t88 = *(const float2*)(at8 + kb + 8);
            split2(elu1(t00.x + L0.x), elu1(t00.y + L0.y), ah[mt][0], av[mt][0]);
            split2(elu1(t80.x + L0.x), elu1(t80.y + L0.y), ah[mt][1], av[mt][1]);
            split2(elu1(t08.x + L8.x), elu1(t08.y + L8.y), ah[mt][2], av[mt][2]);
            split2(elu1(t88.x + L8.x), elu1(t88.y + L8.y), ah[mt][3], av[mt][3]);
        }
        #pragma unroll
        for (int nc = 0; nc < 4; nc++) {
            uint2 whv = wh2[(kc*4 + nc)*32 + lane];
            uint2 wlv = wl2[(kc*4 + nc)*32 + lane];
            uint32_t bh[2] = {whv.x, whv.y};
            uint32_t bl[2] = {wlv.x, wlv.y};
            mma_bf16(D[0][nc], ah[0], bh);
            mma_bf16(D[1][nc], ah[1], bh);
            mma_bf16(D[0][nc], ah[0], bl);
            mma_bf16(D[1][nc], ah[1], bl);
            mma_bf16(D[0][nc], av[0], bh);
            mma_bf16(D[1][nc], av[1], bh);
        }
    }

    // ---- D fragments -> smem (pair-major, pitch 34) ----
    #pragma unroll
    for (int mt = 0; mt < 2; mt++) {
        const int p = w*32 + mt*16 + r;
        #pragma unroll
        for (int nc = 0; nc < 4; nc++) {
            *(float2*)&sm[F_D + p*34 + nc*8 + 2*q]     = make_float2(D[mt][nc][0], D[mt][nc][1]);
            *(float2*)&sm[F_D + (p+8)*34 + nc*8 + 2*q] = make_float2(D[mt][nc][2], D[mt][nc][3]);
        }
    }
    __syncthreads();

    // ---- per-pair epilogue: softmax / elu heads / dist, written back in-place ----
    {
        float* row = &sm[F_D + tid*34];
        float rr[30];
        #pragma unroll
        for (int g = 0; g < 30; g++) rr[g] = row[g];
        float y[10], mx = -1e30f;
        #pragma unroll
        for (int g = 0; g < NG; g++) { y[g] = rr[g] + sm[F_BIAS + g]; mx = fmaxf(mx, y[g]); }
        float ssum = 0.0f;
        #pragma unroll
        for (int g = 0; g < NG; g++) { y[g] = __expf(y[g] - mx); ssum += y[g]; }
        float inv = 1.0f / ssum;
        #pragma unroll
        for (int g = 0; g < NG; g++) row[g] = y[g]*inv;
        #pragma unroll
        for (int g = 0; g < NG; g++) row[10+g] = elu1(rr[10+g] + sm[F_BIAS + 10 + g]) + 1.1f;
        #pragma unroll
        for (int g = 0; g < NG; g++) row[20+g] = elu1(rr[20+g] + sm[F_BIAS + 20 + g]) + 1.0f;
        const int ll = tid >> 5, tl = tid & 31;
        float dx = sm[F_PL + ll*4]   - sm[F_PT + tl*4];
        float dy = sm[F_PL + ll*4+1] - sm[F_PT + tl*4+1];
        float dz = sm[F_PL + ll*4+2] - sm[F_PT + tl*4+2];
        row[30] = sqrtf(dx*dx + dy*dy + dz*dz);
    }
    __syncthreads();

    // ---- coalesced copy-out: pi / sigma / mu (3 x 8 ligs x 320 floats) ----
    #pragma unroll
    for (int i = 0; i < 30; i++) {
        int idx = tid + i*THREADS;          // exactly 7680 total
        int sec = idx / 2560;
        int rem = idx - sec*2560;
        int llc = rem / 320;
        int r2  = rem - llc*320;
        int t   = r2 / 10;
        int g   = r2 - t*10;
        size_t secoff = (sec == 0) ? (size_t)OFF_PI : (sec == 1) ? (size_t)OFF_SIG : (size_t)OFF_MU;
        size_t gaddr = secoff + ((size_t)((b*NL + l0 + llc)*NT) + t0 + t)*NG + g;
        out[gaddr] = sm[F_D + (llc*32 + t)*34 + sec*10 + g];
    }
    // dist + batch id
    {
        size_t pg = (size_t)((b*NL + l0 + (tid >> 5))*NT) + t0 + (tid & 31);
        out[OFF_D  + pg] = sm[F_D + tid*34 + 30];
        out[OFF_CB + pg] = (float)b;
    }
}

// ---------------------------------------------------------------------------
extern "C" void kernel_launch(void* const* d_in, const int* in_sizes, int n_in,
                              void* d_out, int out_size)
{
    (void)in_sizes; (void)n_in; (void)out_size;
    const float* lig_s   = (const float*)d_in[0];
    const float* lig_pos = (const float*)d_in[1];
    const float* pro_s   = (const float*)d_in[3];
    const float* pro_pos = (const float*)d_in[4];
    const float* W1      = (const float*)d_in[6];
    const float* b1      = (const float*)d_in[7];
    const float* bn_g    = (const float*)d_in[8];
    const float* bn_b    = (const float*)d_in[9];
    const float* bn_m    = (const float*)d_in[10];
    const float* bn_v    = (const float*)d_in[11];
    const float* W_pi    = (const float*)d_in[12];
    const float* b_pi    = (const float*)d_in[13];
    const float* W_sig   = (const float*)d_in[14];
    const float* b_sig   = (const float*)d_in[15];
    const float* W_mu    = (const float*)d_in[16];
    const float* b_mu    = (const float*)d_in[17];
    float* out = (float*)d_out;

    cudaFuncSetAttribute(precompute_kernel,
                         cudaFuncAttributeMaxDynamicSharedMemorySize, (int)PRE_SMEM);
    precompute_kernel<<<(NB*NL + NB*NT)/PRE_ROWS, PRE_THREADS, PRE_SMEM>>>(
        lig_s, pro_s, W1, b1, bn_g, bn_b, bn_m, bn_v);

    cudaFuncSetAttribute(pair_kernel,
                         cudaFuncAttributeMaxDynamicSharedMemorySize, SMF*(int)sizeof(float));
    pair_kernel<<<dim3(NT/32, NL/8, NB), THREADS, SMF*sizeof(float)>>>(
        lig_pos, pro_pos, W_pi, b_pi, W_sig, b_sig, W_mu, b_mu, out);
}

// round 6
// speedup vs baseline: 1.9397x; 1.6017x over previous
#include <cuda_runtime.h>
#include <cuda_bf16.h>
#include <math.h>
#include <stdint.h>

#define NB 8
#define NL 48
#define NT 512
#define HD 128
#define NG 10
#define M_TOTAL (NB*NL*NT)          // 196608

#define OFF_PI  0
#define OFF_SIG (M_TOTAL*NG)
#define OFF_MU  (2*M_TOTAL*NG)
#define OFF_D   (3*M_TOTAL*NG)
#define OFF_CB  (3*M_TOTAL*NG + M_TOTAL)

// scratch (device globals: no allocation)
__device__ float g_Al[NB*NL*HD];    // 384 x 128
__device__ float g_At[NB*NT*HD];    // 4096 x 128

__device__ __forceinline__ float elu1(float x) {
    return x > 0.0f ? x : (__expf(x) - 1.0f);
}

// split two fp32 into bf16 hi (truncate) + bf16 lo (round of residual),
// packed k-adjacent: {lo16 = elem k, hi16 = elem k+1}
__device__ __forceinline__ void split2(float e0, float e1, uint32_t& hi, uint32_t& lo) {
    uint32_t u0 = __float_as_uint(e0) & 0xffff0000u;
    uint32_t u1 = __float_as_uint(e1) & 0xffff0000u;
    hi = __byte_perm(u0, u1, 0x7632);
    float f0 = e0 - __uint_as_float(u0);
    float f1 = e1 - __uint_as_float(u1);
    asm("cvt.rn.bf16x2.f32 %0, %1, %2;" : "=r"(lo) : "f"(f1), "f"(f0));
}

// warp-level bf16 MMA, d += a*b  (baseline PTX, works on plain sm_103 target)
__device__ __forceinline__ void mma_bf16(float* d, const uint32_t* a, const uint32_t* b) {
    asm volatile("mma.sync.aligned.m16n8k16.row.col.f32.bf16.bf16.f32 "
        "{%0,%1,%2,%3}, {%4,%5,%6,%7}, {%8,%9}, {%0,%1,%2,%3};"
        : "+f"(d[0]), "+f"(d[1]), "+f"(d[2]), "+f"(d[3])
        : "r"(a[0]), "r"(a[1]), "r"(a[2]), "r"(a[3]), "r"(b[0]), "r"(b[1]));
}

// ---------------------------------------------------------------------------
// Precompute: A_l = s*(lig_s@W1^T + b1 - mean) + beta ;  A_t = s*(pro_s@W1^T)
// 512 threads; warp = 8 output dims x 32 rows -> W reads are warp-uniform
// broadcasts (LDS.128); Xs pitch 129 -> conflict-free column reads.
// ---------------------------------------------------------------------------
#define PRE_ROWS 32
#define PRE_THREADS 512
#define XS_P  129
#define W1T_P 132
#define PRE_SMEM ((PRE_ROWS*XS_P + HD*W1T_P)*sizeof(float))   // 84096 B

__global__ void __launch_bounds__(PRE_THREADS)
precompute_kernel(const float* __restrict__ lig_s, const float* __restrict__ pro_s,
                  const float* __restrict__ W1,    const float* __restrict__ b1,
                  const float* __restrict__ bn_g,  const float* __restrict__ bn_b,
                  const float* __restrict__ bn_m,  const float* __restrict__ bn_v)
{
    extern __shared__ float sm[];
    float* Xs  = sm;                      // [32][129]
    float* W1t = sm + PRE_ROWS*XS_P;      // [128][132] transposed

    const int tid  = threadIdx.x;
    const int w    = tid >> 5;            // 0..15
    const int ln   = tid & 31;
    const int row0 = blockIdx.x * PRE_ROWS;
    const bool is_lig = (row0 < NB*NL);

    // stage 32 input rows (float4 loads, scalar stores to pitch 129)
    const float4* src = is_lig ? (const float4*)(lig_s + (size_t)row0*HD)
                               : (const float4*)(pro_s + (size_t)(row0 - NB*NL)*HD);
    #pragma unroll
    for (int i = 0; i < 2; i++) {
        int idx = tid + i*PRE_THREADS;    // < 1024
        float4 v = src[idx];
        int r = idx >> 5, c = (idx & 31) << 2;
        Xs[r*XS_P + c]   = v.x;
        Xs[r*XS_P + c+1] = v.y;
        Xs[r*XS_P + c+2] = v.z;
        Xs[r*XS_P + c+3] = v.w;
    }
    // stage W1 transposed (coalesced LDG, 4-way-conflict STS — one-time)
    #pragma unroll
    for (int i = 0; i < (HD*HD)/PRE_THREADS; i++) {
        int idx = tid + i*PRE_THREADS;
        int h = idx >> 7, k = idx & (HD-1);
        W1t[k*W1T_P + h] = W1[idx];
    }
    __syncthreads();

    // warp w handles output dims h0..h0+7 for all 32 rows (lane = row)
    const int h0 = w << 3;
    const float* xrow = Xs + ln*XS_P;
    float acc[8];
    #pragma unroll
    for (int j = 0; j < 8; j++) acc[j] = 0.0f;

    #pragma unroll 4
    for (int k = 0; k < HD; k++) {
        float x = xrow[k];
        float4 wa = *(const float4*)(W1t + k*W1T_P + h0);      // uniform -> bcast
        float4 wb = *(const float4*)(W1t + k*W1T_P + h0 + 4);
        acc[0] = fmaf(x, wa.x, acc[0]);
        acc[1] = fmaf(x, wa.y, acc[1]);
        acc[2] = fmaf(x, wa.z, acc[2]);
        acc[3] = fmaf(x, wa.w, acc[3]);
        acc[4] = fmaf(x, wb.x, acc[4]);
        acc[5] = fmaf(x, wb.y, acc[5]);
        acc[6] = fmaf(x, wb.z, acc[6]);
        acc[7] = fmaf(x, wb.w, acc[7]);
    }

    const int row = row0 + ln;
    float o[8];
    if (is_lig) {
        #pragma unroll
        for (int j = 0; j < 8; j++) {
            int h = h0 + j;
            float s = bn_g[h] * rsqrtf(bn_v[h] + 1e-5f);
            o[j] = s * (acc[j] + b1[h] - bn_m[h]) + bn_b[h];
        }
        float4* dst = (float4*)(g_Al + (size_t)row*HD + h0);
        dst[0] = make_float4(o[0], o[1], o[2], o[3]);
        dst[1] = make_float4(o[4], o[5], o[6], o[7]);
    } else {
        #pragma unroll
        for (int j = 0; j < 8; j++) {
            int h = h0 + j;
            float s = bn_g[h] * rsqrtf(bn_v[h] + 1e-5f);
            o[j] = s * acc[j];
        }
        float4* dst = (float4*)(g_At + (size_t)(row - NB*NL)*HD + h0);
        dst[0] = make_float4(o[0], o[1], o[2], o[3]);
        dst[1] = make_float4(o[4], o[5], o[6], o[7]);
    }
}

// ---------------------------------------------------------------------------
// Pair kernel via mma.sync (HMMA bf16, 2-term split, 3 passes).
// Block = 8 ligands x 32 proteins = 256 pairs, 8 warps, warp = 1 lig x 32 prot.
// D-staging buffer UNIONED over At/Al/W region (dead after mainloop) ->
// smem 38.9KB; __launch_bounds__(256,4) -> 4 blocks/SM (occ 50%).
// ---------------------------------------------------------------------------
#define THREADS 256
#define AT_P 136              // float pitch for At/Al staging (mod 32 == 8)

// smem float offsets — F_D overlaps [F_AT..F_WLO) (operands dead after mainloop)
#define F_AT   0              // 32 x 136 = 4352
#define F_AL   4352           // 8 x 136 = 1088
#define F_WHI  5440           // 2048
#define F_WLO  7488           // 2048  -> operands end at 9536
#define F_D    0              // 256 x 34 = 8704  (union)
#define F_BIAS 9536           // 32
#define F_PL   9568           // 8 x 4
#define F_PT   9600           // 32 x 4
#define SMF    9728           // floats -> 38912 bytes

__device__ __forceinline__ float wval(int n, int k, const float* __restrict__ wp,
                                      const float* __restrict__ ws,
                                      const float* __restrict__ wm) {
    if (n < 10) return wp[n*HD + k];
    if (n < 20) return ws[(n-10)*HD + k];
    if (n < 30) return wm[(n-20)*HD + k];
    return 0.0f;
}

__global__ void __launch_bounds__(THREADS, 4)
pair_kernel(const float* __restrict__ lig_pos, const float* __restrict__ pro_pos,
            const float* __restrict__ W_pi,  const float* __restrict__ b_pi,
            const float* __restrict__ W_sig, const float* __restrict__ b_sig,
            const float* __restrict__ W_mu,  const float* __restrict__ b_mu,
            float* __restrict__ out)
{
    extern __shared__ float sm[];
    const int tid  = threadIdx.x;
    const int w    = tid >> 5;           // warp = local ligand 0..7
    const int lane = tid & 31;
    const int r    = lane >> 2;          // 0..7
    const int q    = lane & 3;           // 0..3
    const int b    = blockIdx.z;
    const int l0   = blockIdx.y * 8;
    const int t0   = blockIdx.x * 32;

    // ---- stage At (32 rows) and Al (8 rows), fp32, pitch 136 ----
    {
        const float4* src = (const float4*)(g_At + (size_t)(b*NT + t0)*HD);
        float4* dst = (float4*)&sm[F_AT];          // pitch 34 float4
        #pragma unroll
        for (int i = 0; i < 4; i++) {
            int idx = tid + i*THREADS;              // < 1024
            dst[(idx >> 5)*34 + (idx & 31)] = src[idx];
        }
    }
    {
        const float4* src = (const float4*)(g_Al + (size_t)(b*NL + l0)*HD);
        float4* dst = (float4*)&sm[F_AL];
        dst[(tid >> 5)*34 + (tid & 31)] = src[tid]; // 256 float4
    }
    // ---- pre-split W into per-lane B fragments ----
    {
        uint2* wh = (uint2*)&sm[F_WHI];
        uint2* wl = (uint2*)&sm[F_WLO];
        #pragma unroll
        for (int e = 0; e < 4; e++) {
            int idx = tid + e*THREADS;              // < 1024 = [kc 8][nc 4][lane 32]
            int kc = idx >> 7, nc = (idx >> 5) & 3, ln = idx & 31;
            int n = nc*8 + (ln >> 2);
            int k = kc*16 + 2*(ln & 3);
            float w0 = wval(n, k,   W_pi, W_sig, W_mu);
            float w1 = wval(n, k+1, W_pi, W_sig, W_mu);
            float w8 = wval(n, k+8, W_pi, W_sig, W_mu);
            float w9 = wval(n, k+9, W_pi, W_sig, W_mu);
            uint32_t h0, lo0, h1, lo1;
            split2(w0, w1, h0, lo0);
            split2(w8, w9, h1, lo1);
            wh[idx] = make_uint2(h0, h1);
            wl[idx] = make_uint2(lo0, lo1);
        }
    }
    if (tid < NG) {
        sm[F_BIAS + tid]      = b_pi[tid];
        sm[F_BIAS + 10 + tid] = b_sig[tid];
        sm[F_BIAS + 20 + tid] = b_mu[tid];
    }
    if (tid < 24) {
        int l = tid / 3, c = tid % 3;
        sm[F_PL + l*4 + c] = lig_pos[(size_t)(b*NL + l0 + l)*3 + c];
    }
    if (tid < 96) {
        int t = tid / 3, c = tid % 3;
        sm[F_PT + t*4 + c] = pro_pos[(size_t)(b*NT + t0 + t)*3 + c];
    }
    __syncthreads();

    // ---- mainloop: warp computes D[32 pairs][32 heads] for its ligand ----
    float D[2][4][4];
    #pragma unroll
    for (int mt = 0; mt < 2; mt++)
        #pragma unroll
        for (int nc = 0; nc < 4; nc++)
            #pragma unroll
            for (int j = 0; j < 4; j++) D[mt][nc][j] = 0.0f;

    const float* alr = &sm[F_AL + w*AT_P];
    const uint2* wh2 = (const uint2*)&sm[F_WHI];
    const uint2* wl2 = (const uint2*)&sm[F_WLO];

    #pragma unroll 2
    for (int kc = 0; kc < 8; kc++) {
        const int kb = kc*16 + 2*q;
        float2 L0 = *(const float2*)(alr + kb);
        float2 L8 = *(const float2*)(alr + kb + 8);
        uint32_t ah[2][4], av[2][4];
        #pragma unroll
        for (int mt = 0; mt < 2; mt++) {
            const float* at0 = &sm[F_AT + (mt*16 + r)*AT_P];
            const float* at8 = at0 + 8*AT_P;
            float2 t00 = *(const float2*)(at0 + kb);
            float2 t08 = *(const float2*)(at0 + kb + 8);
            float2 t80 = *(const float2*)(at8 + kb);
            float2 t88 = *(const float2*)(at8 + kb + 8);
            split2(elu1(t00.x + L0.x), elu1(t00.y + L0.y), ah[mt][0], av[mt][0]);
            split2(elu1(t80.x + L0.x), elu1(t80.y + L0.y), ah[mt][1], av[mt][1]);
            split2(elu1(t08.x + L8.x), elu1(t08.y + L8.y), ah[mt][2], av[mt][2]);
            split2(elu1(t88.x + L8.x), elu1(t88.y + L8.y), ah[mt][3], av[mt][3]);
        }
        #pragma unroll
        for (int nc = 0; nc < 4; nc++) {
            uint2 whv = wh2[(kc*4 + nc)*32 + lane];
            uint2 wlv = wl2[(kc*4 + nc)*32 + lane];
            uint32_t bh[2] = {whv.x, whv.y};
            uint32_t bl[2] = {wlv.x, wlv.y};
            mma_bf16(D[0][nc], ah[0], bh);
            mma_bf16(D[1][nc], ah[1], bh);
            mma_bf16(D[0][nc], ah[0], bl);
            mma_bf16(D[1][nc], ah[1], bl);
            mma_bf16(D[0][nc], av[0], bh);
            mma_bf16(D[1][nc], av[1], bh);
        }
    }

    // operands (At/Al/W) dead from here; D buffer overlaps them
    __syncthreads();

    // ---- D fragments -> smem (pair-major, pitch 34) ----
    #pragma unroll
    for (int mt = 0; mt < 2; mt++) {
        const int p = w*32 + mt*16 + r;
        #pragma unroll
        for (int nc = 0; nc < 4; nc++) {
            *(float2*)&sm[F_D + p*34 + nc*8 + 2*q]     = make_float2(D[mt][nc][0], D[mt][nc][1]);
            *(float2*)&sm[F_D + (p+8)*34 + nc*8 + 2*q] = make_float2(D[mt][nc][2], D[mt][nc][3]);
        }
    }
    __syncthreads();

    // ---- per-pair epilogue: softmax / elu heads / dist, written back in-place ----
    {
        float* row = &sm[F_D + tid*34];
        float rr[30];
        #pragma unroll
        for (int g = 0; g < 30; g++) rr[g] = row[g];
        float y[10], mx = -1e30f;
        #pragma unroll
        for (int g = 0; g < NG; g++) { y[g] = rr[g] + sm[F_BIAS + g]; mx = fmaxf(mx, y[g]); }
        float ssum = 0.0f;
        #pragma unroll
        for (int g = 0; g < NG; g++) { y[g] = __expf(y[g] - mx); ssum += y[g]; }
        float inv = 1.0f / ssum;
        #pragma unroll
        for (int g = 0; g < NG; g++) row[g] = y[g]*inv;
        #pragma unroll
        for (int g = 0; g < NG; g++) row[10+g] = elu1(rr[10+g] + sm[F_BIAS + 10 + g]) + 1.1f;
        #pragma unroll
        for (int g = 0; g < NG; g++) row[20+g] = elu1(rr[20+g] + sm[F_BIAS + 20 + g]) + 1.0f;
        const int ll = tid >> 5, tl = tid & 31;
        float dx = sm[F_PL + ll*4]   - sm[F_PT + tl*4];
        float dy = sm[F_PL + ll*4+1] - sm[F_PT + tl*4+1];
        float dz = sm[F_PL + ll*4+2] - sm[F_PT + tl*4+2];
        row[30] = sqrtf(dx*dx + dy*dy + dz*dz);
    }
    __syncthreads();

    // ---- coalesced copy-out: pi / sigma / mu (3 x 8 ligs x 320 floats) ----
    #pragma unroll
    for (int i = 0; i < 30; i++) {
        int idx = tid + i*THREADS;          // exactly 7680 total
        int sec = idx / 2560;
        int rem = idx - sec*2560;
        int llc = rem / 320;
        int r2  = rem - llc*320;
        int t   = r2 / 10;
        int g   = r2 - t*10;
        size_t secoff = (sec == 0) ? (size_t)OFF_PI : (sec == 1) ? (size_t)OFF_SIG : (size_t)OFF_MU;
        size_t gaddr = secoff + ((size_t)((b*NL + l0 + llc)*NT) + t0 + t)*NG + g;
        out[gaddr] = sm[F_D + (llc*32 + t)*34 + sec*10 + g];
    }
    // dist + batch id
    {
        size_t pg = (size_t)((b*NL + l0 + (tid >> 5))*NT) + t0 + (tid & 31);
        out[OFF_D  + pg] = sm[F_D + tid*34 + 30];
        out[OFF_CB + pg] = (float)b;
    }
}

// ---------------------------------------------------------------------------
extern "C" void kernel_launch(void* const* d_in, const int* in_sizes, int n_in,
                              void* d_out, int out_size)
{
    (void)in_sizes; (void)n_in; (void)out_size;
    const float* lig_s   = (const float*)d_in[0];
    const float* lig_pos = (const float*)d_in[1];
    const float* pro_s   = (const float*)d_in[3];
    const float* pro_pos = (const float*)d_in[4];
    const float* W1      = (const float*)d_in[6];
    const float* b1      = (const float*)d_in[7];
    const float* bn_g    = (const float*)d_in[8];
    const float* bn_b    = (const float*)d_in[9];
    const float* bn_m    = (const float*)d_in[10];
    const float* bn_v    = (const float*)d_in[11];
    const float* W_pi    = (const float*)d_in[12];
    const float* b_pi    = (const float*)d_in[13];
    const float* W_sig   = (const float*)d_in[14];
    const float* b_sig   = (const float*)d_in[15];
    const float* W_mu    = (const float*)d_in[16];
    const float* b_mu    = (const float*)d_in[17];
    float* out = (float*)d_out;

    cudaFuncSetAttribute(precompute_kernel,
                         cudaFuncAttributeMaxDynamicSharedMemorySize, (int)PRE_SMEM);
    precompute_kernel<<<(NB*NL + NB*NT)/PRE_ROWS, PRE_THREADS, PRE_SMEM>>>(
        lig_s, pro_s, W1, b1, bn_g, bn_b, bn_m, bn_v);

    pair_kernel<<<dim3(NT/32, NL/8, NB), THREADS, SMF*sizeof(float)>>>(
        lig_pos, pro_pos, W_pi, b_pi, W_sig, b_sig, W_mu, b_mu, out);
}